// round 3
// baseline (speedup 1.0000x reference)
#include <cuda_runtime.h>
#include <math.h>

// Problem constants
#define BN   4
#define CN   256
#define HN   64
#define WN   64
#define HWN  4096
#define CHWN (CN * HWN)     // 1048576
#define SCALE 0.0625f       // 1/sqrt(256)

// ---------------------------------------------------------------------------
// Scratch (device globals; no allocations allowed)
// ---------------------------------------------------------------------------
__device__ float g_Q[BN * CHWN];     // [b][c][n]
__device__ float g_K[BN * CHWN];     // [b][c][n]
__device__ float g_V[BN * CHWN];     // [b][c][n]
__device__ float g_colmax[BN * HWN]; // max over n of soft[b,n,m]  (positive)
__device__ float g_Qmask[4 * HWN];   // indexed by (c%4)*4096 + n
__device__ float g_m2[BN * HN];      // indexed by b*64 + h_k

// ---------------------------------------------------------------------------
// 0) zero colmax each call (atomics accumulate into it)
// ---------------------------------------------------------------------------
__global__ void init_kernel() {
    int i = blockIdx.x * blockDim.x + threadIdx.x;
    if (i < BN * HWN) g_colmax[i] = 0.0f;
}

// ---------------------------------------------------------------------------
// 1) fused QKV 1x1-conv GEMM:  X[b,o,n] = sum_c W[o,c] * fuse[b,c,n] + bias[o]
//    Block: 64(o) x 64(n) tile for one batch, all three weight sets.
//    256 threads, 4x4 micro-tile per thread per output.
// ---------------------------------------------------------------------------
__global__ __launch_bounds__(256) void qkv_kernel(
    const float* __restrict__ fuse,
    const float* __restrict__ Wq, const float* __restrict__ bq,
    const float* __restrict__ Wk, const float* __restrict__ bk,
    const float* __restrict__ Wv, const float* __restrict__ bv)
{
    __shared__ float sF [16][68];
    __shared__ float sWq[16][68];
    __shared__ float sWk[16][68];
    __shared__ float sWv[16][68];

    const int b  = blockIdx.z;
    const int o0 = blockIdx.y * 64;
    const int n0 = blockIdx.x * 64;
    const int tid = threadIdx.x;
    const int tx = tid & 15;      // n sub-tile
    const int ty = tid >> 4;      // o sub-tile

    float aq[4][4], ak[4][4], av[4][4];
#pragma unroll
    for (int i = 0; i < 4; i++)
#pragma unroll
        for (int j = 0; j < 4; j++) { aq[i][j] = 0.f; ak[i][j] = 0.f; av[i][j] = 0.f; }

    const float* fbase = fuse + (size_t)b * CHWN + n0;

    // load indices
    const int f_ck = tid >> 4;           // 0..15
    const int f_nn = (tid & 15) * 4;     // 0..60
    const int w_oo = tid >> 2;           // 0..63
    const int w_ck = (tid & 3) * 4;      // 0,4,8,12

    for (int c0 = 0; c0 < CN; c0 += 16) {
        __syncthreads();
        // fuse chunk [16 c][64 n] — one float4 per thread
        {
            float4 f4 = *reinterpret_cast<const float4*>(&fbase[(c0 + f_ck) * HWN + f_nn]);
            *reinterpret_cast<float4*>(&sF[f_ck][f_nn]) = f4;
        }
        // weight chunks [16 c][64 o] (transposed into smem)
        {
            float4 q4 = *reinterpret_cast<const float4*>(&Wq[(o0 + w_oo) * CN + c0 + w_ck]);
            float4 k4 = *reinterpret_cast<const float4*>(&Wk[(o0 + w_oo) * CN + c0 + w_ck]);
            float4 v4 = *reinterpret_cast<const float4*>(&Wv[(o0 + w_oo) * CN + c0 + w_ck]);
            sWq[w_ck + 0][w_oo] = q4.x; sWq[w_ck + 1][w_oo] = q4.y;
            sWq[w_ck + 2][w_oo] = q4.z; sWq[w_ck + 3][w_oo] = q4.w;
            sWk[w_ck + 0][w_oo] = k4.x; sWk[w_ck + 1][w_oo] = k4.y;
            sWk[w_ck + 2][w_oo] = k4.z; sWk[w_ck + 3][w_oo] = k4.w;
            sWv[w_ck + 0][w_oo] = v4.x; sWv[w_ck + 1][w_oo] = v4.y;
            sWv[w_ck + 2][w_oo] = v4.z; sWv[w_ck + 3][w_oo] = v4.w;
        }
        __syncthreads();
#pragma unroll
        for (int ck = 0; ck < 16; ck++) {
            float4 bf4 = *reinterpret_cast<const float4*>(&sF [ck][tx * 4]);
            float4 q4  = *reinterpret_cast<const float4*>(&sWq[ck][ty * 4]);
            float4 k4  = *reinterpret_cast<const float4*>(&sWk[ck][ty * 4]);
            float4 v4  = *reinterpret_cast<const float4*>(&sWv[ck][ty * 4]);
            float bfr[4] = {bf4.x, bf4.y, bf4.z, bf4.w};
            float qr [4] = {q4.x,  q4.y,  q4.z,  q4.w };
            float kr [4] = {k4.x,  k4.y,  k4.z,  k4.w };
            float vr [4] = {v4.x,  v4.y,  v4.z,  v4.w };
#pragma unroll
            for (int i = 0; i < 4; i++)
#pragma unroll
                for (int j = 0; j < 4; j++) {
                    aq[i][j] += qr[i] * bfr[j];
                    ak[i][j] += kr[i] * bfr[j];
                    av[i][j] += vr[i] * bfr[j];
                }
        }
    }

    // epilogue: add bias, write coalesced float4 rows
#pragma unroll
    for (int i = 0; i < 4; i++) {
        const int o = o0 + ty * 4 + i;
        const float bq_ = bq[o], bk_ = bk[o], bv_ = bv[o];
        const size_t base = (size_t)b * CHWN + (size_t)o * HWN + n0 + tx * 4;
        float4 oq = make_float4(aq[i][0] + bq_, aq[i][1] + bq_, aq[i][2] + bq_, aq[i][3] + bq_);
        float4 ok = make_float4(ak[i][0] + bk_, ak[i][1] + bk_, ak[i][2] + bk_, ak[i][3] + bk_);
        float4 ov = make_float4(av[i][0] + bv_, av[i][1] + bv_, av[i][2] + bv_, av[i][3] + bv_);
        *reinterpret_cast<float4*>(&g_Q[base]) = oq;
        *reinterpret_cast<float4*>(&g_K[base]) = ok;
        *reinterpret_cast<float4*>(&g_V[base]) = ov;
    }
}

// ---------------------------------------------------------------------------
// 2) Q_mask[(c%4)*4096 + n] = max over b (4) and q (64, c = 4q + c%4) of Q[b,c,n]
// ---------------------------------------------------------------------------
__global__ void qmask_kernel() {
    int col = blockIdx.x * blockDim.x + threadIdx.x;   // 0..16383
    if (col >= 4 * HWN) return;
    int cm = col >> 12;           // c % 4
    int n  = col & (HWN - 1);
    float mx = -3.4e38f;
#pragma unroll 4
    for (int b = 0; b < BN; b++) {
        const float* base = &g_Q[(size_t)b * CHWN + n];
        for (int q = 0; q < 64; q++)
            mx = fmaxf(mx, base[(size_t)(4 * q + cm) * HWN]);
    }
    g_Qmask[col] = mx;
}

// ---------------------------------------------------------------------------
// 3) scores + batch-softmax + column-max reduction.
//    Block computes scores[b, n0:n0+64, m0:m0+64] for ALL 4 batches
//    (softmax is over the batch axis), then reduces max over n into g_colmax.
//    Per thread: 4(n) x 4(m) x 4(b) = 64 fp32 accumulators.
// ---------------------------------------------------------------------------
__global__ __launch_bounds__(256) void scores_kernel() {
    __shared__ float sQ[4][16][68];
    __shared__ float sK[4][16][68];
    __shared__ int   sRed[4 * 64];

    const int m0 = blockIdx.x * 64;
    const int n0 = blockIdx.y * 64;
    const int tid = threadIdx.x;
    const int tx = tid & 15;      // m sub-tile
    const int ty = tid >> 4;      // n sub-tile

    float acc[4][4][4];           // [b][i=n][j=m]
#pragma unroll
    for (int b = 0; b < 4; b++)
#pragma unroll
        for (int i = 0; i < 4; i++)
#pragma unroll
            for (int j = 0; j < 4; j++) acc[b][i][j] = 0.f;

    sRed[tid] = 0;                // 256 == 4*64

    for (int c0 = 0; c0 < CN; c0 += 16) {
        __syncthreads();
#pragma unroll
        for (int r = 0; r < 4; r++) {
            int idx = r * 256 + tid;          // 0..1023
            int bb = idx >> 8;
            int ck = (idx >> 4) & 15;
            int n4 = (idx & 15) * 4;
            size_t goff = (size_t)bb * CHWN + (size_t)(c0 + ck) * HWN;
            *reinterpret_cast<float4*>(&sQ[bb][ck][n4]) =
                *reinterpret_cast<const float4*>(&g_Q[goff + n0 + n4]);
            *reinterpret_cast<float4*>(&sK[bb][ck][n4]) =
                *reinterpret_cast<const float4*>(&g_K[goff + m0 + n4]);
        }
        __syncthreads();
#pragma unroll
        for (int ck = 0; ck < 16; ck++) {
#pragma unroll
            for (int b = 0; b < 4; b++) {
                float4 q4 = *reinterpret_cast<const float4*>(&sQ[b][ck][ty * 4]);
                float4 k4 = *reinterpret_cast<const float4*>(&sK[b][ck][tx * 4]);
                float qr[4] = {q4.x, q4.y, q4.z, q4.w};
                float kr[4] = {k4.x, k4.y, k4.z, k4.w};
#pragma unroll
                for (int i = 0; i < 4; i++)
#pragma unroll
                    for (int j = 0; j < 4; j++)
                        acc[b][i][j] += qr[i] * kr[j];
            }
        }
    }

    // softmax over b per (n,m), track max over n per (b,m)
    float lm[4][4];               // [b][j]
#pragma unroll
    for (int b = 0; b < 4; b++)
#pragma unroll
        for (int j = 0; j < 4; j++) lm[b][j] = 0.f;

#pragma unroll
    for (int i = 0; i < 4; i++) {
#pragma unroll
        for (int j = 0; j < 4; j++) {
            float s[4], e[4];
            float mx = -3.4e38f;
#pragma unroll
            for (int b = 0; b < 4; b++) { s[b] = acc[b][i][j] * SCALE; mx = fmaxf(mx, s[b]); }
            float sum = 0.f;
#pragma unroll
            for (int b = 0; b < 4; b++) { e[b] = __expf(s[b] - mx); sum += e[b]; }
            float inv = 1.0f / sum;
#pragma unroll
            for (int b = 0; b < 4; b++) lm[b][j] = fmaxf(lm[b][j], e[b] * inv);
        }
    }

    // block reduce over n (soft > 0, so float-as-int max is monotone)
#pragma unroll
    for (int b = 0; b < 4; b++)
#pragma unroll
        for (int j = 0; j < 4; j++)
            atomicMax(&sRed[b * 64 + tx * 4 + j], __float_as_int(lm[b][j]));
    __syncthreads();

    {
        int b  = tid >> 6;
        int mm = tid & 63;
        atomicMax(reinterpret_cast<int*>(&g_colmax[(size_t)b * HWN + m0 + mm]), sRed[tid]);
    }
}

// ---------------------------------------------------------------------------
// 4) m2[b*64 + h_k] = max over w_k of colmax[b, h_k*64 + w_k]
// ---------------------------------------------------------------------------
__global__ void m2_kernel() {
    int r = threadIdx.x;          // 0..255, single block
    int b = r >> 6, hk = r & 63;
    const float* base = &g_colmax[(size_t)b * HWN + hk * 64];
    float mx = 0.f;
#pragma unroll
    for (int wk = 0; wk < 64; wk++) mx = fmaxf(mx, base[wk]);
    g_m2[r] = mx;
}

// ---------------------------------------------------------------------------
// 5) out[b,c,n] = V * (1 + m2[b*64 + c/4] * Qmask[(c%4)*4096 + n])
// ---------------------------------------------------------------------------
__global__ void out_kernel(float* __restrict__ out) {
    int f = blockIdx.x * blockDim.x + threadIdx.x;     // float4 index
    if (f >= BN * CHWN / 4) return;
    int n4 = f & (HWN / 4 - 1);
    int bc = f >> 10;
    int c  = bc & (CN - 1);
    int b  = bc >> 8;
    int n  = n4 * 4;
    float m2v = g_m2[b * 64 + (c >> 2)];
    float4 qm = *reinterpret_cast<const float4*>(&g_Qmask[(c & 3) * HWN + n]);
    float4 v  = reinterpret_cast<const float4*>(g_V)[f];
    float4 o;
    o.x = v.x * fmaf(m2v, qm.x, 1.0f);
    o.y = v.y * fmaf(m2v, qm.y, 1.0f);
    o.z = v.z * fmaf(m2v, qm.z, 1.0f);
    o.w = v.w * fmaf(m2v, qm.w, 1.0f);
    reinterpret_cast<float4*>(out)[f] = o;
}

// ---------------------------------------------------------------------------
extern "C" void kernel_launch(void* const* d_in, const int* in_sizes, int n_in,
                              void* d_out, int out_size) {
    const float* fuse = (const float*)d_in[0];
    const float* Wq   = (const float*)d_in[1];
    const float* bq   = (const float*)d_in[2];
    const float* Wk   = (const float*)d_in[3];
    const float* bk   = (const float*)d_in[4];
    const float* Wv   = (const float*)d_in[5];
    const float* bv   = (const float*)d_in[6];
    float* out = (float*)d_out;

    init_kernel<<<(BN * HWN + 255) / 256, 256>>>();

    dim3 gq(HWN / 64, CN / 64, BN);
    qkv_kernel<<<gq, 256>>>(fuse, Wq, bq, Wk, bk, Wv, bv);

    qmask_kernel<<<(4 * HWN + 255) / 256, 256>>>();

    dim3 gs(HWN / 64, HWN / 64);
    scores_kernel<<<gs, 256>>>();

    m2_kernel<<<1, 256>>>();

    out_kernel<<<(BN * CHWN / 4 + 255) / 256, 256>>>(out);
}

// round 5
// speedup vs baseline: 2.1439x; 2.1439x over previous
#include <cuda_runtime.h>
#include <math.h>
#include <stdint.h>

// Problem constants
#define BN   4
#define CN   256
#define HN   64
#define WN   64
#define HWN  4096
#define CHWN (CN * HWN)     // 1048576
#define SCALE 0.0625f       // 1/sqrt(256)

// ---------------------------------------------------------------------------
// Scratch (device globals; no allocations allowed)
// ---------------------------------------------------------------------------
__device__ float g_Q [BN * CHWN];    // fp32 Q (for Q_mask)
__device__ float g_Qt[BN * CHWN];    // tf32-rounded Q (for scores MMA)
__device__ float g_Kt[BN * CHWN];    // tf32-rounded K (for scores MMA)
__device__ float g_V [BN * CHWN];
__device__ float g_colmax[BN * HWN]; // max over n of soft[b,n,m]  (positive)
__device__ float g_Qmask[4 * HWN];   // indexed by (c%4)*4096 + n
__device__ float g_m2[BN * HN];      // indexed by b*64 + h_k

__device__ __forceinline__ float tf32r(float x) {
    uint32_t r;
    asm("cvt.rna.tf32.f32 %0, %1;" : "=r"(r) : "f"(x));
    return __uint_as_float(r);
}

__device__ __forceinline__ void cpasync16(void* dst, const void* src) {
    unsigned s = (unsigned)__cvta_generic_to_shared(dst);
    asm volatile("cp.async.cg.shared.global [%0], [%1], 16;\n" :: "r"(s), "l"(src));
}
__device__ __forceinline__ void cpcommit() { asm volatile("cp.async.commit_group;\n"); }
__device__ __forceinline__ void cpwait0()  { asm volatile("cp.async.wait_group 0;\n"); }

// ---------------------------------------------------------------------------
// 0) zero colmax each call (atomics accumulate into it)
// ---------------------------------------------------------------------------
__global__ void init_kernel() {
    int i = blockIdx.x * blockDim.x + threadIdx.x;
    if (i < BN * HWN) g_colmax[i] = 0.0f;
}

// ---------------------------------------------------------------------------
// 1) fused QKV 1x1-conv GEMM:  X[b,o,n] = sum_c W[o,c] * fuse[b,c,n] + bias[o]
// ---------------------------------------------------------------------------
__global__ __launch_bounds__(256) void qkv_kernel(
    const float* __restrict__ fuse,
    const float* __restrict__ Wq, const float* __restrict__ bq,
    const float* __restrict__ Wk, const float* __restrict__ bk,
    const float* __restrict__ Wv, const float* __restrict__ bv)
{
    __shared__ float sF [16][68];
    __shared__ float sWq[16][68];
    __shared__ float sWk[16][68];
    __shared__ float sWv[16][68];

    const int b  = blockIdx.z;
    const int o0 = blockIdx.y * 64;
    const int n0 = blockIdx.x * 64;
    const int tid = threadIdx.x;
    const int tx = tid & 15;      // n sub-tile
    const int ty = tid >> 4;      // o sub-tile

    float aq[4][4], ak[4][4], av[4][4];
#pragma unroll
    for (int i = 0; i < 4; i++)
#pragma unroll
        for (int j = 0; j < 4; j++) { aq[i][j] = 0.f; ak[i][j] = 0.f; av[i][j] = 0.f; }

    const float* fbase = fuse + (size_t)b * CHWN + n0;

    const int f_ck = tid >> 4;
    const int f_nn = (tid & 15) * 4;
    const int w_oo = tid >> 2;
    const int w_ck = (tid & 3) * 4;

    for (int c0 = 0; c0 < CN; c0 += 16) {
        __syncthreads();
        {
            float4 f4 = *reinterpret_cast<const float4*>(&fbase[(c0 + f_ck) * HWN + f_nn]);
            *reinterpret_cast<float4*>(&sF[f_ck][f_nn]) = f4;
        }
        {
            float4 q4 = *reinterpret_cast<const float4*>(&Wq[(o0 + w_oo) * CN + c0 + w_ck]);
            float4 k4 = *reinterpret_cast<const float4*>(&Wk[(o0 + w_oo) * CN + c0 + w_ck]);
            float4 v4 = *reinterpret_cast<const float4*>(&Wv[(o0 + w_oo) * CN + c0 + w_ck]);
            sWq[w_ck + 0][w_oo] = q4.x; sWq[w_ck + 1][w_oo] = q4.y;
            sWq[w_ck + 2][w_oo] = q4.z; sWq[w_ck + 3][w_oo] = q4.w;
            sWk[w_ck + 0][w_oo] = k4.x; sWk[w_ck + 1][w_oo] = k4.y;
            sWk[w_ck + 2][w_oo] = k4.z; sWk[w_ck + 3][w_oo] = k4.w;
            sWv[w_ck + 0][w_oo] = v4.x; sWv[w_ck + 1][w_oo] = v4.y;
            sWv[w_ck + 2][w_oo] = v4.z; sWv[w_ck + 3][w_oo] = v4.w;
        }
        __syncthreads();
#pragma unroll
        for (int ck = 0; ck < 16; ck++) {
            float4 bf4 = *reinterpret_cast<const float4*>(&sF [ck][tx * 4]);
            float4 q4  = *reinterpret_cast<const float4*>(&sWq[ck][ty * 4]);
            float4 k4  = *reinterpret_cast<const float4*>(&sWk[ck][ty * 4]);
            float4 v4  = *reinterpret_cast<const float4*>(&sWv[ck][ty * 4]);
            float bfr[4] = {bf4.x, bf4.y, bf4.z, bf4.w};
            float qr [4] = {q4.x,  q4.y,  q4.z,  q4.w };
            float kr [4] = {k4.x,  k4.y,  k4.z,  k4.w };
            float vr [4] = {v4.x,  v4.y,  v4.z,  v4.w };
#pragma unroll
            for (int i = 0; i < 4; i++)
#pragma unroll
                for (int j = 0; j < 4; j++) {
                    aq[i][j] += qr[i] * bfr[j];
                    ak[i][j] += kr[i] * bfr[j];
                    av[i][j] += vr[i] * bfr[j];
                }
        }
    }

#pragma unroll
    for (int i = 0; i < 4; i++) {
        const int o = o0 + ty * 4 + i;
        const float bq_ = bq[o], bk_ = bk[o], bv_ = bv[o];
        const size_t base = (size_t)b * CHWN + (size_t)o * HWN + n0 + tx * 4;
        float4 oq = make_float4(aq[i][0] + bq_, aq[i][1] + bq_, aq[i][2] + bq_, aq[i][3] + bq_);
        float4 ok = make_float4(ak[i][0] + bk_, ak[i][1] + bk_, ak[i][2] + bk_, ak[i][3] + bk_);
        float4 ov = make_float4(av[i][0] + bv_, av[i][1] + bv_, av[i][2] + bv_, av[i][3] + bv_);
        float4 qt = make_float4(tf32r(oq.x), tf32r(oq.y), tf32r(oq.z), tf32r(oq.w));
        float4 kt = make_float4(tf32r(ok.x), tf32r(ok.y), tf32r(ok.z), tf32r(ok.w));
        *reinterpret_cast<float4*>(&g_Q [base]) = oq;
        *reinterpret_cast<float4*>(&g_Qt[base]) = qt;
        *reinterpret_cast<float4*>(&g_Kt[base]) = kt;
        *reinterpret_cast<float4*>(&g_V [base]) = ov;
    }
}

// ---------------------------------------------------------------------------
// 2) Q_mask[(c%4)*4096 + n] = max over b (4) and q (64, c = 4q + c%4) of Q[b,c,n]
// ---------------------------------------------------------------------------
__global__ void qmask_kernel() {
    int col = blockIdx.x * blockDim.x + threadIdx.x;   // 0..16383
    if (col >= 4 * HWN) return;
    int cm = col >> 12;           // c % 4
    int n  = col & (HWN - 1);
    float mx = -3.4e38f;
#pragma unroll 4
    for (int b = 0; b < BN; b++) {
        const float* base = &g_Q[(size_t)b * CHWN + n];
        for (int q = 0; q < 64; q++)
            mx = fmaxf(mx, base[(size_t)(4 * q + cm) * HWN]);
    }
    g_Qmask[col] = mx;
}

// ---------------------------------------------------------------------------
// 3) scores + batch-softmax + column-max reduction  (tf32 tensor cores)
//    Block: 64(n) x 64(m) x 4(b), 8 warps = 4(n-tiles of 16) x 2(m-halves of 32).
//    Each warp: 16n x 32m x 4b via mma.sync.m16n8k8.tf32, 64 f32 acc/thread.
//    cp.async double-buffered smem, KC=16 per stage, k-row pad 72 (conflict-free).
// ---------------------------------------------------------------------------
#define KC 16
#define KPAD 72
#define SMEM_OP_FLOATS (2 * 4 * KC * KPAD)   // per operand, both stages = 9216
#define SCORES_SMEM_BYTES (2 * SMEM_OP_FLOATS * 4 + 256 * 4)

__global__ __launch_bounds__(256) void scores_kernel() {
    extern __shared__ float smem[];
    float* sQ = smem;                       // [stage][b][k][KPAD]
    float* sK = smem + SMEM_OP_FLOATS;      // [stage][b][k][KPAD]
    int*   sRed = (int*)(smem + 2 * SMEM_OP_FLOATS);  // [4][64]

    const int m0 = blockIdx.x * 64;
    const int n0 = blockIdx.y * 64;
    const int tid = threadIdx.x;
    const int warp = tid >> 5;
    const int lane = tid & 31;
    const int gid = lane >> 2;    // 0..7
    const int tg  = lane & 3;     // 0..3
    const int wn = warp & 3;      // n-tile (16 rows each)
    const int wm = warp >> 2;     // m-half (32 cols each)

    if (tid < 256) sRed[tid] = 0;

    float acc[4][4][4];           // [b][j(m8 tile)][e(frag elem)]
#pragma unroll
    for (int b = 0; b < 4; b++)
#pragma unroll
        for (int j = 0; j < 4; j++)
#pragma unroll
            for (int e = 0; e < 4; e++) acc[b][j][e] = 0.f;

    // ---- async load of one KC-chunk into stage s ----
    auto issue_chunk = [&](int c, int s) {
        const int kbase = c * KC;
#pragma unroll
        for (int r = 0; r < 4; r++) {
            int idx = r * 256 + tid;          // 0..1023 float4 slots
            int bb = idx >> 8;
            int ck = (idx >> 4) & 15;
            int n4 = (idx & 15) << 2;
            size_t goff = (size_t)bb * CHWN + (size_t)(kbase + ck) * HWN;
            int soff = (((s << 2) + bb) * KC + ck) * KPAD + n4;
            cpasync16(&sQ[soff], &g_Qt[goff + n0 + n4]);
            cpasync16(&sK[soff], &g_Kt[goff + m0 + n4]);
        }
    };

    issue_chunk(0, 0);
    cpcommit();

    const int arow = wn * 16 + gid;
    const int bcol0 = wm * 32 + gid;

    for (int c = 0; c < CN / KC; c++) {
        cpwait0();
        __syncthreads();
        if (c < CN / KC - 1) { issue_chunk(c + 1, (c + 1) & 1); cpcommit(); }

        const int s = c & 1;
#pragma unroll
        for (int ks = 0; ks < KC; ks += 8) {
#pragma unroll
            for (int b = 0; b < 4; b++) {
                const float* qb = &sQ[(((s << 2) + b) * KC) * KPAD];
                const float* kb = &sK[(((s << 2) + b) * KC) * KPAD];
                unsigned A0 = __float_as_uint(qb[(ks + tg    ) * KPAD + arow]);
                unsigned A1 = __float_as_uint(qb[(ks + tg    ) * KPAD + arow + 8]);
                unsigned A2 = __float_as_uint(qb[(ks + tg + 4) * KPAD + arow]);
                unsigned A3 = __float_as_uint(qb[(ks + tg + 4) * KPAD + arow + 8]);
#pragma unroll
                for (int j = 0; j < 4; j++) {
                    unsigned B0 = __float_as_uint(kb[(ks + tg    ) * KPAD + bcol0 + j * 8]);
                    unsigned B1 = __float_as_uint(kb[(ks + tg + 4) * KPAD + bcol0 + j * 8]);
                    asm volatile(
                        "mma.sync.aligned.m16n8k8.row.col.f32.tf32.tf32.f32 "
                        "{%0,%1,%2,%3}, {%4,%5,%6,%7}, {%8,%9}, {%0,%1,%2,%3};"
                        : "+f"(acc[b][j][0]), "+f"(acc[b][j][1]),
                          "+f"(acc[b][j][2]), "+f"(acc[b][j][3])
                        : "r"(A0), "r"(A1), "r"(A2), "r"(A3), "r"(B0), "r"(B1));
                }
            }
        }
        __syncthreads();
    }

    // ---- epilogue: softmax over b per (n,m); fold max over the thread's two
    //      n-rows; atomicMax into per-block column max sRed[b][m_local] ----
#pragma unroll
    for (int j = 0; j < 4; j++) {
#pragma unroll
        for (int p = 0; p < 2; p++) {         // column parity (2*tg + p)
            float colv[4];
#pragma unroll
            for (int b = 0; b < 4; b++) colv[b] = 0.f;
#pragma unroll
            for (int rr = 0; rr < 2; rr++) {  // the two n-rows (gid, gid+8)
                int e = rr * 2 + p;
                float sv[4];
                float mx = -3.4e38f;
#pragma unroll
                for (int b = 0; b < 4; b++) { sv[b] = acc[b][j][e] * SCALE; mx = fmaxf(mx, sv[b]); }
                float ex[4], sum = 0.f;
#pragma unroll
                for (int b = 0; b < 4; b++) { ex[b] = __expf(sv[b] - mx); sum += ex[b]; }
                float inv = 1.0f / sum;
#pragma unroll
                for (int b = 0; b < 4; b++) colv[b] = fmaxf(colv[b], ex[b] * inv);
            }
            int m_local = wm * 32 + j * 8 + tg * 2 + p;
#pragma unroll
            for (int b = 0; b < 4; b++)
                atomicMax(&sRed[b * 64 + m_local], __float_as_int(colv[b]));
        }
    }
    __syncthreads();

    if (tid < 256) {
        int b  = tid >> 6;
        int mm = tid & 63;
        atomicMax(reinterpret_cast<int*>(&g_colmax[(size_t)b * HWN + m0 + mm]), sRed[tid]);
    }
}

// ---------------------------------------------------------------------------
// 4) m2[b*64 + h_k] = max over w_k of colmax[b, h_k*64 + w_k]
// ---------------------------------------------------------------------------
__global__ void m2_kernel() {
    int r = threadIdx.x;          // 0..255, single block
    int b = r >> 6, hk = r & 63;
    const float* base = &g_colmax[(size_t)b * HWN + hk * 64];
    float mx = 0.f;
#pragma unroll
    for (int wk = 0; wk < 64; wk++) mx = fmaxf(mx, base[wk]);
    g_m2[r] = mx;
}

// ---------------------------------------------------------------------------
// 5) out[b,c,n] = V * (1 + m2[b*64 + c/4] * Qmask[(c%4)*4096 + n])
// ---------------------------------------------------------------------------
__global__ void out_kernel(float* __restrict__ out) {
    int f = blockIdx.x * blockDim.x + threadIdx.x;     // float4 index
    if (f >= BN * CHWN / 4) return;
    int n4 = f & (HWN / 4 - 1);
    int bc = f >> 10;
    int c  = bc & (CN - 1);
    int b  = bc >> 8;
    int n  = n4 * 4;
    float m2v = g_m2[b * 64 + (c >> 2)];
    float4 qm = *reinterpret_cast<const float4*>(&g_Qmask[(c & 3) * HWN + n]);
    float4 v  = reinterpret_cast<const float4*>(g_V)[f];
    float4 o;
    o.x = v.x * fmaf(m2v, qm.x, 1.0f);
    o.y = v.y * fmaf(m2v, qm.y, 1.0f);
    o.z = v.z * fmaf(m2v, qm.z, 1.0f);
    o.w = v.w * fmaf(m2v, qm.w, 1.0f);
    reinterpret_cast<float4*>(out)[f] = o;
}

// ---------------------------------------------------------------------------
extern "C" void kernel_launch(void* const* d_in, const int* in_sizes, int n_in,
                              void* d_out, int out_size) {
    const float* fuse = (const float*)d_in[0];
    const float* Wq   = (const float*)d_in[1];
    const float* bq   = (const float*)d_in[2];
    const float* Wk   = (const float*)d_in[3];
    const float* bk   = (const float*)d_in[4];
    const float* Wv   = (const float*)d_in[5];
    const float* bv   = (const float*)d_in[6];
    float* out = (float*)d_out;

    cudaFuncSetAttribute(scores_kernel,
                         cudaFuncAttributeMaxDynamicSharedMemorySize,
                         SCORES_SMEM_BYTES);

    init_kernel<<<(BN * HWN + 255) / 256, 256>>>();

    dim3 gq(HWN / 64, CN / 64, BN);
    qkv_kernel<<<gq, 256>>>(fuse, Wq, bq, Wk, bk, Wv, bv);

    qmask_kernel<<<(4 * HWN + 255) / 256, 256>>>();

    dim3 gs(HWN / 64, HWN / 64);
    scores_kernel<<<gs, 256, SCORES_SMEM_BYTES>>>();

    m2_kernel<<<1, 256>>>();

    out_kernel<<<(BN * CHWN / 4 + 255) / 256, 256>>>(out);
}

// round 7
// speedup vs baseline: 2.5370x; 1.1833x over previous
#include <cuda_runtime.h>
#include <cuda_bf16.h>
#include <math.h>
#include <stdint.h>

// Problem constants
#define BN   4
#define CN   256
#define HN   64
#define WN   64
#define HWN  4096
#define CHWN (CN * HWN)     // 1048576
#define SCALE 0.0625f       // 1/sqrt(256)

// ---------------------------------------------------------------------------
// Scratch (device globals; no allocations allowed)
// ---------------------------------------------------------------------------
__device__ float g_Q [BN * CHWN];            // fp32 Q, [b][c][n]  (for Q_mask)
__device__ float g_V [BN * CHWN];            // fp32 V, [b][c][n]
__device__ __nv_bfloat16 g_Qb[BN * CHWN];    // bf16 Q, TRANSPOSED [b][n][c]
__device__ __nv_bfloat16 g_Kb[BN * CHWN];    // bf16 K, TRANSPOSED [b][m][c]
__device__ float g_colmax[BN * HWN];         // max over n of soft[b,n,m]  (positive)
__device__ float g_Qmask[4 * HWN];           // indexed by (c%4)*4096 + n
__device__ float g_m2[BN * HN];              // indexed by b*64 + h_k

__device__ __forceinline__ void cpasync16(void* dst, const void* src) {
    unsigned s = (unsigned)__cvta_generic_to_shared(dst);
    asm volatile("cp.async.cg.shared.global [%0], [%1], 16;\n" :: "r"(s), "l"(src));
}
__device__ __forceinline__ void cpcommit() { asm volatile("cp.async.commit_group;\n"); }
__device__ __forceinline__ void cpwait0()  { asm volatile("cp.async.wait_group 0;\n"); }

// ---------------------------------------------------------------------------
// 0) zero colmax each call (atomics accumulate into it)
// ---------------------------------------------------------------------------
__global__ void init_kernel() {
    int i = blockIdx.x * blockDim.x + threadIdx.x;
    if (i < BN * HWN) g_colmax[i] = 0.0f;
}

// ---------------------------------------------------------------------------
// 1) fused QKV 1x1-conv GEMM:  X[b,o,n] = sum_c W[o,c] * fuse[b,c,n] + bias[o]
//    Writes: g_Q, g_V fp32 [b][c][n];  g_Qb, g_Kb bf16 transposed [b][n][c].
// ---------------------------------------------------------------------------
__global__ __launch_bounds__(256) void qkv_kernel(
    const float* __restrict__ fuse,
    const float* __restrict__ Wq, const float* __restrict__ bq,
    const float* __restrict__ Wk, const float* __restrict__ bk,
    const float* __restrict__ Wv, const float* __restrict__ bv)
{
    __shared__ float sF [16][68];
    __shared__ float sWq[16][68];
    __shared__ float sWk[16][68];
    __shared__ float sWv[16][68];

    const int b  = blockIdx.z;
    const int o0 = blockIdx.y * 64;
    const int n0 = blockIdx.x * 64;
    const int tid = threadIdx.x;
    const int tx = tid & 15;      // n sub-tile
    const int ty = tid >> 4;      // o sub-tile

    float aq[4][4], ak[4][4], av[4][4];
#pragma unroll
    for (int i = 0; i < 4; i++)
#pragma unroll
        for (int j = 0; j < 4; j++) { aq[i][j] = 0.f; ak[i][j] = 0.f; av[i][j] = 0.f; }

    const float* fbase = fuse + (size_t)b * CHWN + n0;

    const int f_ck = tid >> 4;
    const int f_nn = (tid & 15) * 4;
    const int w_oo = tid >> 2;
    const int w_ck = (tid & 3) * 4;

    for (int c0 = 0; c0 < CN; c0 += 16) {
        __syncthreads();
        {
            float4 f4 = *reinterpret_cast<const float4*>(&fbase[(c0 + f_ck) * HWN + f_nn]);
            *reinterpret_cast<float4*>(&sF[f_ck][f_nn]) = f4;
        }
        {
            float4 q4 = *reinterpret_cast<const float4*>(&Wq[(o0 + w_oo) * CN + c0 + w_ck]);
            float4 k4 = *reinterpret_cast<const float4*>(&Wk[(o0 + w_oo) * CN + c0 + w_ck]);
            float4 v4 = *reinterpret_cast<const float4*>(&Wv[(o0 + w_oo) * CN + c0 + w_ck]);
            sWq[w_ck + 0][w_oo] = q4.x; sWq[w_ck + 1][w_oo] = q4.y;
            sWq[w_ck + 2][w_oo] = q4.z; sWq[w_ck + 3][w_oo] = q4.w;
            sWk[w_ck + 0][w_oo] = k4.x; sWk[w_ck + 1][w_oo] = k4.y;
            sWk[w_ck + 2][w_oo] = k4.z; sWk[w_ck + 3][w_oo] = k4.w;
            sWv[w_ck + 0][w_oo] = v4.x; sWv[w_ck + 1][w_oo] = v4.y;
            sWv[w_ck + 2][w_oo] = v4.z; sWv[w_ck + 3][w_oo] = v4.w;
        }
        __syncthreads();
#pragma unroll
        for (int ck = 0; ck < 16; ck++) {
            float4 bf4 = *reinterpret_cast<const float4*>(&sF [ck][tx * 4]);
            float4 q4  = *reinterpret_cast<const float4*>(&sWq[ck][ty * 4]);
            float4 k4  = *reinterpret_cast<const float4*>(&sWk[ck][ty * 4]);
            float4 v4  = *reinterpret_cast<const float4*>(&sWv[ck][ty * 4]);
            float bfr[4] = {bf4.x, bf4.y, bf4.z, bf4.w};
            float qr [4] = {q4.x,  q4.y,  q4.z,  q4.w };
            float kr [4] = {k4.x,  k4.y,  k4.z,  k4.w };
            float vr [4] = {v4.x,  v4.y,  v4.z,  v4.w };
#pragma unroll
            for (int i = 0; i < 4; i++)
#pragma unroll
                for (int j = 0; j < 4; j++) {
                    aq[i][j] += qr[i] * bfr[j];
                    ak[i][j] += kr[i] * bfr[j];
                    av[i][j] += vr[i] * bfr[j];
                }
        }
    }

    float bqv[4], bkv[4], bvv[4];
#pragma unroll
    for (int i = 0; i < 4; i++) {
        int o = o0 + ty * 4 + i;
        bqv[i] = bq[o]; bkv[i] = bk[o]; bvv[i] = bv[o];
    }

    // fp32 Q and V in [c][n]
#pragma unroll
    for (int i = 0; i < 4; i++) {
        const size_t base = (size_t)b * CHWN + (size_t)(o0 + ty * 4 + i) * HWN + n0 + tx * 4;
        float4 oq = make_float4(aq[i][0] + bqv[i], aq[i][1] + bqv[i], aq[i][2] + bqv[i], aq[i][3] + bqv[i]);
        float4 ov = make_float4(av[i][0] + bvv[i], av[i][1] + bvv[i], av[i][2] + bvv[i], av[i][3] + bvv[i]);
        *reinterpret_cast<float4*>(&g_Q[base]) = oq;
        *reinterpret_cast<float4*>(&g_V[base]) = ov;
    }

    // bf16 Q/K transposed [n][c]: 4 consecutive c per thread = 8-byte store
#pragma unroll
    for (int j = 0; j < 4; j++) {
        const int n = n0 + tx * 4 + j;
        const size_t tbase = (size_t)b * CHWN + (size_t)n * CN + o0 + ty * 4;
        __nv_bfloat162 q01 = __floats2bfloat162_rn(aq[0][j] + bqv[0], aq[1][j] + bqv[1]);
        __nv_bfloat162 q23 = __floats2bfloat162_rn(aq[2][j] + bqv[2], aq[3][j] + bqv[3]);
        __nv_bfloat162 k01 = __floats2bfloat162_rn(ak[0][j] + bkv[0], ak[1][j] + bkv[1]);
        __nv_bfloat162 k23 = __floats2bfloat162_rn(ak[2][j] + bkv[2], ak[3][j] + bkv[3]);
        uint2 qp = make_uint2(*(uint32_t*)&q01, *(uint32_t*)&q23);
        uint2 kp = make_uint2(*(uint32_t*)&k01, *(uint32_t*)&k23);
        *reinterpret_cast<uint2*>(&g_Qb[tbase]) = qp;
        *reinterpret_cast<uint2*>(&g_Kb[tbase]) = kp;
    }
}

// ---------------------------------------------------------------------------
// 2) Q_mask[(c%4)*4096 + n] = max over b (4) and q (64, c = 4q + c%4) of Q[b,c,n]
// ---------------------------------------------------------------------------
__global__ void qmask_kernel() {
    int col = blockIdx.x * blockDim.x + threadIdx.x;   // 0..16383
    if (col >= 4 * HWN) return;
    int cm = col >> 12;           // c % 4
    int n  = col & (HWN - 1);
    float mx = -3.4e38f;
#pragma unroll 4
    for (int b = 0; b < BN; b++) {
        const float* base = &g_Q[(size_t)b * CHWN + n];
        for (int q = 0; q < 64; q++)
            mx = fmaxf(mx, base[(size_t)(4 * q + cm) * HWN]);
    }
    g_Qmask[col] = mx;
}

// ---------------------------------------------------------------------------
// 3) scores + batch-softmax + column-max reduction  (bf16 mma.sync m16n8k16)
//    Block: 64(n) x 64(m) x 4(b), 8 warps = 4(n-tiles of 16) x 2(m-halves of 32).
//    Each warp: 16n x 32m x 4b, 64 f32 acc/thread.
//    SMEM: KC=32 bf16 rows at pitch 20 b32 (all-32-banks-distinct fragment loads),
//    double-buffered cp.async.  2 CTAs/SM (81 KB smem, <=128 regs).
// ---------------------------------------------------------------------------
#define KC      32
#define PITCH   20                      // b32 per row (16 data + 4 pad)
#define TILE32  (64 * PITCH)            // per-b tile, b32 units = 1280
#define OPST32  (4 * TILE32)            // per operand per stage = 5120
#define SK_BASE (2 * OPST32)            // K after Q's two stages
#define RED32   (4 * OPST32)            // sRed after K's two stages
#define SCORES_SMEM_BYTES (RED32 * 4 + 256 * 4)

__global__ __launch_bounds__(256, 2) void scores_kernel() {
    extern __shared__ uint32_t smem[];
    uint32_t* sQ = smem;                 // [stage][b][row 64][PITCH]
    uint32_t* sK = smem + SK_BASE;
    int* sRed = (int*)(smem + RED32);    // [4][64]

    const int m0 = blockIdx.x * 64;
    const int n0 = blockIdx.y * 64;
    const int tid = threadIdx.x;
    const int warp = tid >> 5;
    const int lane = tid & 31;
    const int gid = lane >> 2;    // 0..7
    const int tg  = lane & 3;     // 0..3
    const int wn = warp & 3;      // n-tile (16 rows each)
    const int wm = warp >> 2;     // m-half (32 cols each)

    sRed[tid] = 0;

    float acc[4][4][4];           // [b][j(m8 tile)][e(frag elem)]
#pragma unroll
    for (int b = 0; b < 4; b++)
#pragma unroll
        for (int j = 0; j < 4; j++)
#pragma unroll
            for (int e = 0; e < 4; e++) acc[b][j][e] = 0.f;

    // ---- async load of one KC=32 chunk into stage s ----
    // per operand: 4b x 64 rows x 64B (4 x 16B segments) = 1024 cp.asyncs
    auto issue_chunk = [&](int c, int s) {
        const int kb = c * KC;           // bf16 offset within row
#pragma unroll
        for (int it = 0; it < 4; it++) {
            int slot = it * 256 + tid;   // 0..1023
            int b   = slot >> 8;
            int row = (slot >> 2) & 63;
            int seg = slot & 3;          // 16B segment (8 bf16)
            int d = s * OPST32 + b * TILE32 + row * PITCH + seg * 4;
            cpasync16(&sQ[d], &g_Qb[(size_t)b * CHWN + (size_t)(n0 + row) * CN + kb + seg * 8]);
            cpasync16(&sK[d], &g_Kb[(size_t)b * CHWN + (size_t)(m0 + row) * CN + kb + seg * 8]);
        }
    };

    issue_chunk(0, 0);
    cpcommit();

    const int arow = wn * 16 + gid;

    for (int c = 0; c < CN / KC; c++) {
        cpwait0();
        __syncthreads();
        if (c < CN / KC - 1) { issue_chunk(c + 1, (c + 1) & 1); cpcommit(); }

        const int s = c & 1;
#pragma unroll
        for (int kk = 0; kk < 2; kk++) {           // two k16 steps per chunk
            const int kp = kk * 8 + tg;            // bf16-pair index within row
#pragma unroll
            for (int b = 0; b < 4; b++) {
                const uint32_t* qb = &sQ[s * OPST32 + b * TILE32];
                const uint32_t* kbp = &sK[s * OPST32 + b * TILE32];
                uint32_t A0 = qb[(arow    ) * PITCH + kp];
                uint32_t A1 = qb[(arow + 8) * PITCH + kp];
                uint32_t A2 = qb[(arow    ) * PITCH + kp + 4];
                uint32_t A3 = qb[(arow + 8) * PITCH + kp + 4];
#pragma unroll
                for (int j = 0; j < 4; j++) {
                    const int brow = wm * 32 + j * 8 + gid;
                    uint32_t B0 = kbp[brow * PITCH + kp];
                    uint32_t B1 = kbp[brow * PITCH + kp + 4];
                    asm volatile(
                        "mma.sync.aligned.m16n8k16.row.col.f32.bf16.bf16.f32 "
                        "{%0,%1,%2,%3}, {%4,%5,%6,%7}, {%8,%9}, {%0,%1,%2,%3};"
                        : "+f"(acc[b][j][0]), "+f"(acc[b][j][1]),
                          "+f"(acc[b][j][2]), "+f"(acc[b][j][3])
                        : "r"(A0), "r"(A1), "r"(A2), "r"(A3), "r"(B0), "r"(B1));
                }
            }
        }
        __syncthreads();
    }

    // ---- epilogue: softmax over b per (n,m); fold max over the thread's two
    //      n-rows; atomicMax into per-block column max sRed[b][m_local] ----
#pragma unroll
    for (int j = 0; j < 4; j++) {
#pragma unroll
        for (int p = 0; p < 2; p++) {         // column parity (2*tg + p)
            float colv[4];
#pragma unroll
            for (int b = 0; b < 4; b++) colv[b] = 0.f;
#pragma unroll
            for (int rr = 0; rr < 2; rr++) {  // the two n-rows (gid, gid+8)
                int e = rr * 2 + p;
                float sv[4];
                float mx = -3.4e38f;
#pragma unroll
                for (int b = 0; b < 4; b++) { sv[b] = acc[b][j][e] * SCALE; mx = fmaxf(mx, sv[b]); }
                float ex[4], sum = 0.f;
#pragma unroll
                for (int b = 0; b < 4; b++) { ex[b] = __expf(sv[b] - mx); sum += ex[b]; }
                float inv = 1.0f / sum;
#pragma unroll
                for (int b = 0; b < 4; b++) colv[b] = fmaxf(colv[b], ex[b] * inv);
            }
            int m_local = wm * 32 + j * 8 + tg * 2 + p;
#pragma unroll
            for (int b = 0; b < 4; b++)
                atomicMax(&sRed[b * 64 + m_local], __float_as_int(colv[b]));
        }
    }
    __syncthreads();

    {
        int b  = tid >> 6;
        int mm = tid & 63;
        atomicMax(reinterpret_cast<int*>(&g_colmax[(size_t)b * HWN + m0 + mm]), sRed[tid]);
    }
}

// ---------------------------------------------------------------------------
// 4) m2[b*64 + h_k] = max over w_k of colmax[b, h_k*64 + w_k]
// ---------------------------------------------------------------------------
__global__ void m2_kernel() {
    int r = threadIdx.x;          // 0..255, single block
    int b = r >> 6, hk = r & 63;
    const float* base = &g_colmax[(size_t)b * HWN + hk * 64];
    float mx = 0.f;
#pragma unroll
    for (int wk = 0; wk < 64; wk++) mx = fmaxf(mx, base[wk]);
    g_m2[r] = mx;
}

// ---------------------------------------------------------------------------
// 5) out[b,c,n] = V * (1 + m2[b*64 + c/4] * Qmask[(c%4)*4096 + n])
// ---------------------------------------------------------------------------
__global__ void out_kernel(float* __restrict__ out) {
    int f = blockIdx.x * blockDim.x + threadIdx.x;     // float4 index
    if (f >= BN * CHWN / 4) return;
    int n4 = f & (HWN / 4 - 1);
    int bc = f >> 10;
    int c  = bc & (CN - 1);
    int b  = bc >> 8;
    int n  = n4 * 4;
    float m2v = g_m2[b * 64 + (c >> 2)];
    float4 qm = *reinterpret_cast<const float4*>(&g_Qmask[(c & 3) * HWN + n]);
    float4 v  = reinterpret_cast<const float4*>(g_V)[f];
    float4 o;
    o.x = v.x * fmaf(m2v, qm.x, 1.0f);
    o.y = v.y * fmaf(m2v, qm.y, 1.0f);
    o.z = v.z * fmaf(m2v, qm.z, 1.0f);
    o.w = v.w * fmaf(m2v, qm.w, 1.0f);
    reinterpret_cast<float4*>(out)[f] = o;
}

// ---------------------------------------------------------------------------
extern "C" void kernel_launch(void* const* d_in, const int* in_sizes, int n_in,
                              void* d_out, int out_size) {
    const float* fuse = (const float*)d_in[0];
    const float* Wq   = (const float*)d_in[1];
    const float* bq   = (const float*)d_in[2];
    const float* Wk   = (const float*)d_in[3];
    const float* bk   = (const float*)d_in[4];
    const float* Wv   = (const float*)d_in[5];
    const float* bv   = (const float*)d_in[6];
    float* out = (float*)d_out;

    cudaFuncSetAttribute(scores_kernel,
                         cudaFuncAttributeMaxDynamicSharedMemorySize,
                         SCORES_SMEM_BYTES);

    init_kernel<<<(BN * HWN + 255) / 256, 256>>>();

    dim3 gq(HWN / 64, CN / 64, BN);
    qkv_kernel<<<gq, 256>>>(fuse, Wq, bq, Wk, bk, Wv, bv);

    qmask_kernel<<<(4 * HWN + 255) / 256, 256>>>();

    dim3 gs(HWN / 64, HWN / 64);
    scores_kernel<<<gs, 256, SCORES_SMEM_BYTES>>>();

    m2_kernel<<<1, 256>>>();

    out_kernel<<<(BN * CHWN / 4 + 255) / 256, 256>>>(out);
}

// round 8
// speedup vs baseline: 2.7069x; 1.0670x over previous
#include <cuda_runtime.h>
#include <cuda_bf16.h>
#include <math.h>
#include <stdint.h>

// Problem constants
#define BN   4
#define CN   256
#define HN   64
#define WN   64
#define HWN  4096
#define CHWN (CN * HWN)     // 1048576
#define SCALE 0.0625f       // 1/sqrt(256)

// ---------------------------------------------------------------------------
// Scratch (device globals; no allocations allowed)
// ---------------------------------------------------------------------------
__device__ float g_Q [BN * CHWN];            // fp32 Q, [b][c][n]  (for Q_mask)
__device__ float g_V [BN * CHWN];            // fp32 V, [b][c][n]
__device__ __nv_bfloat16 g_Qb[BN * CHWN];    // bf16 Q, TRANSPOSED [b][n][c]
__device__ __nv_bfloat16 g_Kb[BN * CHWN];    // bf16 K, TRANSPOSED [b][m][c]
__device__ float g_colmax[BN * HWN];         // max over n of soft[b,n,m]  (positive)
__device__ float g_Qmask[4 * HWN];           // indexed by (c%4)*4096 + n
__device__ float g_m2[BN * HN];              // indexed by b*64 + h_k

__device__ __forceinline__ void cpasync16(void* dst, const void* src) {
    unsigned s = (unsigned)__cvta_generic_to_shared(dst);
    asm volatile("cp.async.cg.shared.global [%0], [%1], 16;\n" :: "r"(s), "l"(src));
}
__device__ __forceinline__ void cpcommit() { asm volatile("cp.async.commit_group;\n"); }
__device__ __forceinline__ void cpwait0()  { asm volatile("cp.async.wait_group 0;\n"); }

__device__ __forceinline__ void ldmx4(uint32_t& r0, uint32_t& r1, uint32_t& r2, uint32_t& r3,
                                      uint32_t addr) {
    asm volatile("ldmatrix.sync.aligned.m8n8.x4.shared.b16 {%0,%1,%2,%3}, [%4];"
                 : "=r"(r0), "=r"(r1), "=r"(r2), "=r"(r3) : "r"(addr));
}

// ---------------------------------------------------------------------------
// 0) zero colmax each call (atomics accumulate into it)
// ---------------------------------------------------------------------------
__global__ void init_kernel() {
    int i = blockIdx.x * blockDim.x + threadIdx.x;
    if (i < BN * HWN) g_colmax[i] = 0.0f;
}

// ---------------------------------------------------------------------------
// 1) fused QKV 1x1-conv GEMM:  X[b,o,n] = sum_c W[o,c] * fuse[b,c,n] + bias[o]
//    Writes: g_Q, g_V fp32 [b][c][n];  g_Qb, g_Kb bf16 transposed [b][n][c].
// ---------------------------------------------------------------------------
__global__ __launch_bounds__(256) void qkv_kernel(
    const float* __restrict__ fuse,
    const float* __restrict__ Wq, const float* __restrict__ bq,
    const float* __restrict__ Wk, const float* __restrict__ bk,
    const float* __restrict__ Wv, const float* __restrict__ bv)
{
    __shared__ float sF [16][68];
    __shared__ float sWq[16][68];
    __shared__ float sWk[16][68];
    __shared__ float sWv[16][68];

    const int b  = blockIdx.z;
    const int o0 = blockIdx.y * 64;
    const int n0 = blockIdx.x * 64;
    const int tid = threadIdx.x;
    const int tx = tid & 15;      // n sub-tile
    const int ty = tid >> 4;      // o sub-tile

    float aq[4][4], ak[4][4], av[4][4];
#pragma unroll
    for (int i = 0; i < 4; i++)
#pragma unroll
        for (int j = 0; j < 4; j++) { aq[i][j] = 0.f; ak[i][j] = 0.f; av[i][j] = 0.f; }

    const float* fbase = fuse + (size_t)b * CHWN + n0;

    const int f_ck = tid >> 4;
    const int f_nn = (tid & 15) * 4;
    const int w_oo = tid >> 2;
    const int w_ck = (tid & 3) * 4;

    for (int c0 = 0; c0 < CN; c0 += 16) {
        __syncthreads();
        {
            float4 f4 = *reinterpret_cast<const float4*>(&fbase[(c0 + f_ck) * HWN + f_nn]);
            *reinterpret_cast<float4*>(&sF[f_ck][f_nn]) = f4;
        }
        {
            float4 q4 = *reinterpret_cast<const float4*>(&Wq[(o0 + w_oo) * CN + c0 + w_ck]);
            float4 k4 = *reinterpret_cast<const float4*>(&Wk[(o0 + w_oo) * CN + c0 + w_ck]);
            float4 v4 = *reinterpret_cast<const float4*>(&Wv[(o0 + w_oo) * CN + c0 + w_ck]);
            sWq[w_ck + 0][w_oo] = q4.x; sWq[w_ck + 1][w_oo] = q4.y;
            sWq[w_ck + 2][w_oo] = q4.z; sWq[w_ck + 3][w_oo] = q4.w;
            sWk[w_ck + 0][w_oo] = k4.x; sWk[w_ck + 1][w_oo] = k4.y;
            sWk[w_ck + 2][w_oo] = k4.z; sWk[w_ck + 3][w_oo] = k4.w;
            sWv[w_ck + 0][w_oo] = v4.x; sWv[w_ck + 1][w_oo] = v4.y;
            sWv[w_ck + 2][w_oo] = v4.z; sWv[w_ck + 3][w_oo] = v4.w;
        }
        __syncthreads();
#pragma unroll
        for (int ck = 0; ck < 16; ck++) {
            float4 bf4 = *reinterpret_cast<const float4*>(&sF [ck][tx * 4]);
            float4 q4  = *reinterpret_cast<const float4*>(&sWq[ck][ty * 4]);
            float4 k4  = *reinterpret_cast<const float4*>(&sWk[ck][ty * 4]);
            float4 v4  = *reinterpret_cast<const float4*>(&sWv[ck][ty * 4]);
            float bfr[4] = {bf4.x, bf4.y, bf4.z, bf4.w};
            float qr [4] = {q4.x,  q4.y,  q4.z,  q4.w };
            float kr [4] = {k4.x,  k4.y,  k4.z,  k4.w };
            float vr [4] = {v4.x,  v4.y,  v4.z,  v4.w };
#pragma unroll
            for (int i = 0; i < 4; i++)
#pragma unroll
                for (int j = 0; j < 4; j++) {
                    aq[i][j] += qr[i] * bfr[j];
                    ak[i][j] += kr[i] * bfr[j];
                    av[i][j] += vr[i] * bfr[j];
                }
        }
    }

    float bqv[4], bkv[4], bvv[4];
#pragma unroll
    for (int i = 0; i < 4; i++) {
        int o = o0 + ty * 4 + i;
        bqv[i] = bq[o]; bkv[i] = bk[o]; bvv[i] = bv[o];
    }

    // fp32 Q and V in [c][n]
#pragma unroll
    for (int i = 0; i < 4; i++) {
        const size_t base = (size_t)b * CHWN + (size_t)(o0 + ty * 4 + i) * HWN + n0 + tx * 4;
        float4 oq = make_float4(aq[i][0] + bqv[i], aq[i][1] + bqv[i], aq[i][2] + bqv[i], aq[i][3] + bqv[i]);
        float4 ov = make_float4(av[i][0] + bvv[i], av[i][1] + bvv[i], av[i][2] + bvv[i], av[i][3] + bvv[i]);
        *reinterpret_cast<float4*>(&g_Q[base]) = oq;
        *reinterpret_cast<float4*>(&g_V[base]) = ov;
    }

    // bf16 Q/K transposed [n][c]: 4 consecutive c per thread = 8-byte store
#pragma unroll
    for (int j = 0; j < 4; j++) {
        const int n = n0 + tx * 4 + j;
        const size_t tbase = (size_t)b * CHWN + (size_t)n * CN + o0 + ty * 4;
        __nv_bfloat162 q01 = __floats2bfloat162_rn(aq[0][j] + bqv[0], aq[1][j] + bqv[1]);
        __nv_bfloat162 q23 = __floats2bfloat162_rn(aq[2][j] + bqv[2], aq[3][j] + bqv[3]);
        __nv_bfloat162 k01 = __floats2bfloat162_rn(ak[0][j] + bkv[0], ak[1][j] + bkv[1]);
        __nv_bfloat162 k23 = __floats2bfloat162_rn(ak[2][j] + bkv[2], ak[3][j] + bkv[3]);
        uint2 qp = make_uint2(*(uint32_t*)&q01, *(uint32_t*)&q23);
        uint2 kp = make_uint2(*(uint32_t*)&k01, *(uint32_t*)&k23);
        *reinterpret_cast<uint2*>(&g_Qb[tbase]) = qp;
        *reinterpret_cast<uint2*>(&g_Kb[tbase]) = kp;
    }
}

// ---------------------------------------------------------------------------
// 2) Q_mask[(c%4)*4096 + n] = max over b (4) and q (64, c = 4q + c%4) of Q[b,c,n]
// ---------------------------------------------------------------------------
__global__ void qmask_kernel() {
    int col = blockIdx.x * blockDim.x + threadIdx.x;   // 0..16383
    if (col >= 4 * HWN) return;
    int cm = col >> 12;           // c % 4
    int n  = col & (HWN - 1);
    float mx = -3.4e38f;
#pragma unroll 4
    for (int b = 0; b < BN; b++) {
        const float* base = &g_Q[(size_t)b * CHWN + n];
        for (int q = 0; q < 64; q++)
            mx = fmaxf(mx, base[(size_t)(4 * q + cm) * HWN]);
    }
    g_Qmask[col] = mx;
}

// ---------------------------------------------------------------------------
// 3) scores + batch-softmax + column-max reduction  (bf16 mma + ldmatrix)
//    Block: 64(n) x 64(m) x 4(b), 8 warps = 4(n-tiles of 16) x 2(m-halves of 32).
//    SMEM rows at 80B pitch (conflict-free for ldmatrix), double-buffered.
//    One __syncthreads per chunk.  2 CTAs/SM.
// ---------------------------------------------------------------------------
#define KC      32
#define PITCH   20                      // b32 per row (16 data + 4 pad)
#define TILE32  (64 * PITCH)            // per-b tile, b32 units = 1280
#define OPST32  (4 * TILE32)            // per operand per stage = 5120
#define SK_BASE (2 * OPST32)            // K after Q's two stages
#define RED32   (4 * OPST32)            // sRed after K's two stages
#define SCORES_SMEM_BYTES (RED32 * 4 + 256 * 4)

__global__ __launch_bounds__(256, 2) void scores_kernel() {
    extern __shared__ uint32_t smem[];
    uint32_t* sQ = smem;                 // [stage][b][row 64][PITCH]
    uint32_t* sK = smem + SK_BASE;
    int* sRed = (int*)(smem + RED32);    // [4][64]

    const uint32_t sQ_u = (uint32_t)__cvta_generic_to_shared(sQ);
    const uint32_t sK_u = (uint32_t)__cvta_generic_to_shared(sK);

    const int m0 = blockIdx.x * 64;
    const int n0 = blockIdx.y * 64;
    const int tid = threadIdx.x;
    const int warp = tid >> 5;
    const int lane = tid & 31;
    const int tg  = lane & 3;     // 0..3
    const int wn = warp & 3;      // n-tile (16 rows each)
    const int wm = warp >> 2;     // m-half (32 cols each)

    sRed[tid] = 0;

    float acc[4][4][4];           // [b][j(m8 tile)][e(frag elem)]
#pragma unroll
    for (int b = 0; b < 4; b++)
#pragma unroll
        for (int j = 0; j < 4; j++)
#pragma unroll
            for (int e = 0; e < 4; e++) acc[b][j][e] = 0.f;

    // ldmatrix lane-address offsets (bytes within one b-tile)
    // A (x4): lanes 0-15 -> rows wn*16 + (lane&15), k-half 0; lanes 16-31 -> same rows, k-half 1
    const uint32_t a_off = (uint32_t)((wn * 16 + (lane & 15)) * 80 + (lane >> 4) * 16);
    // B (x4 = 2 j-tiles): row = wm*32 + (lane>>4)*8 + (lane&7), k-half = (lane>>3)&1
    const uint32_t b_off = (uint32_t)((wm * 32 + ((lane >> 4) << 3) + (lane & 7)) * 80 +
                                      ((lane >> 3) & 1) * 16);

    // ---- async load of one KC=32 chunk into stage s ----
    auto issue_chunk = [&](int c, int s) {
        const int kb = c * KC;           // bf16 offset within row
#pragma unroll
        for (int it = 0; it < 4; it++) {
            int slot = it * 256 + tid;   // 0..1023
            int b   = slot >> 8;
            int row = (slot >> 2) & 63;
            int seg = slot & 3;          // 16B segment (8 bf16)
            int d = s * OPST32 + b * TILE32 + row * PITCH + seg * 4;
            cpasync16(&sQ[d], &g_Qb[(size_t)b * CHWN + (size_t)(n0 + row) * CN + kb + seg * 8]);
            cpasync16(&sK[d], &g_Kb[(size_t)b * CHWN + (size_t)(m0 + row) * CN + kb + seg * 8]);
        }
    };

    issue_chunk(0, 0);
    cpcommit();

    for (int c = 0; c < CN / KC; c++) {
        cpwait0();
        __syncthreads();      // single barrier per chunk: orders prior compute
                              // (stage s reads) before this iter's cp.async writes
        if (c < CN / KC - 1) { issue_chunk(c + 1, (c + 1) & 1); cpcommit(); }

        const int s = c & 1;
        const uint32_t qbase = sQ_u + (uint32_t)(s * OPST32 * 4);
        const uint32_t kbase = sK_u + (uint32_t)(s * OPST32 * 4);
#pragma unroll
        for (int kk = 0; kk < 2; kk++) {           // two k16 steps per chunk
            const uint32_t kbyte = kk * 32;
#pragma unroll
            for (int b = 0; b < 4; b++) {
                const uint32_t tb = (uint32_t)(b * TILE32 * 4);
                uint32_t A0, A1, A2, A3;
                ldmx4(A0, A1, A2, A3, qbase + tb + a_off + kbyte);
#pragma unroll
                for (int jp = 0; jp < 2; jp++) {   // 2 j-tiles per ldmatrix
                    uint32_t B0, B1, B2, B3;
                    ldmx4(B0, B1, B2, B3, kbase + tb + b_off + jp * 1280 + kbyte);
                    const int j0 = jp * 2;
                    asm volatile(
                        "mma.sync.aligned.m16n8k16.row.col.f32.bf16.bf16.f32 "
                        "{%0,%1,%2,%3}, {%4,%5,%6,%7}, {%8,%9}, {%0,%1,%2,%3};"
                        : "+f"(acc[b][j0][0]), "+f"(acc[b][j0][1]),
                          "+f"(acc[b][j0][2]), "+f"(acc[b][j0][3])
                        : "r"(A0), "r"(A1), "r"(A2), "r"(A3), "r"(B0), "r"(B1));
                    asm volatile(
                        "mma.sync.aligned.m16n8k16.row.col.f32.bf16.bf16.f32 "
                        "{%0,%1,%2,%3}, {%4,%5,%6,%7}, {%8,%9}, {%0,%1,%2,%3};"
                        : "+f"(acc[b][j0+1][0]), "+f"(acc[b][j0+1][1]),
                          "+f"(acc[b][j0+1][2]), "+f"(acc[b][j0+1][3])
                        : "r"(A0), "r"(A1), "r"(A2), "r"(A3), "r"(B2), "r"(B3));
                }
            }
        }
    }

    // ---- epilogue: softmax over b per (n,m); fold max over the thread's two
    //      n-rows; atomicMax into per-block column max sRed[b][m_local] ----
#pragma unroll
    for (int j = 0; j < 4; j++) {
#pragma unroll
        for (int p = 0; p < 2; p++) {         // column parity (2*tg + p)
            float colv[4];
#pragma unroll
            for (int b = 0; b < 4; b++) colv[b] = 0.f;
#pragma unroll
            for (int rr = 0; rr < 2; rr++) {  // the two n-rows (gid, gid+8)
                int e = rr * 2 + p;
                float sv[4];
                float mx = -3.4e38f;
#pragma unroll
                for (int b = 0; b < 4; b++) { sv[b] = acc[b][j][e] * SCALE; mx = fmaxf(mx, sv[b]); }
                float ex[4], sum = 0.f;
#pragma unroll
                for (int b = 0; b < 4; b++) { ex[b] = __expf(sv[b] - mx); sum += ex[b]; }
                float inv = 1.0f / sum;
#pragma unroll
                for (int b = 0; b < 4; b++) colv[b] = fmaxf(colv[b], ex[b] * inv);
            }
            int m_local = wm * 32 + j * 8 + tg * 2 + p;
#pragma unroll
            for (int b = 0; b < 4; b++)
                atomicMax(&sRed[b * 64 + m_local], __float_as_int(colv[b]));
        }
    }
    __syncthreads();

    {
        int b  = tid >> 6;
        int mm = tid & 63;
        atomicMax(reinterpret_cast<int*>(&g_colmax[(size_t)b * HWN + m0 + mm]), sRed[tid]);
    }
}

// ---------------------------------------------------------------------------
// 4) m2[b*64 + h_k] = max over w_k of colmax[b, h_k*64 + w_k]
// ---------------------------------------------------------------------------
__global__ void m2_kernel() {
    int r = threadIdx.x;          // 0..255, single block
    int b = r >> 6, hk = r & 63;
    const float* base = &g_colmax[(size_t)b * HWN + hk * 64];
    float mx = 0.f;
#pragma unroll
    for (int wk = 0; wk < 64; wk++) mx = fmaxf(mx, base[wk]);
    g_m2[r] = mx;
}

// ---------------------------------------------------------------------------
// 5) out[b,c,n] = V * (1 + m2[b*64 + c/4] * Qmask[(c%4)*4096 + n])
// ---------------------------------------------------------------------------
__global__ void out_kernel(float* __restrict__ out) {
    int f = blockIdx.x * blockDim.x + threadIdx.x;     // float4 index
    if (f >= BN * CHWN / 4) return;
    int n4 = f & (HWN / 4 - 1);
    int bc = f >> 10;
    int c  = bc & (CN - 1);
    int b  = bc >> 8;
    int n  = n4 * 4;
    float m2v = g_m2[b * 64 + (c >> 2)];
    float4 qm = *reinterpret_cast<const float4*>(&g_Qmask[(c & 3) * HWN + n]);
    float4 v  = reinterpret_cast<const float4*>(g_V)[f];
    float4 o;
    o.x = v.x * fmaf(m2v, qm.x, 1.0f);
    o.y = v.y * fmaf(m2v, qm.y, 1.0f);
    o.z = v.z * fmaf(m2v, qm.z, 1.0f);
    o.w = v.w * fmaf(m2v, qm.w, 1.0f);
    reinterpret_cast<float4*>(out)[f] = o;
}

// ---------------------------------------------------------------------------
extern "C" void kernel_launch(void* const* d_in, const int* in_sizes, int n_in,
                              void* d_out, int out_size) {
    const float* fuse = (const float*)d_in[0];
    const float* Wq   = (const float*)d_in[1];
    const float* bq   = (const float*)d_in[2];
    const float* Wk   = (const float*)d_in[3];
    const float* bk   = (const float*)d_in[4];
    const float* Wv   = (const float*)d_in[5];
    const float* bv   = (const float*)d_in[6];
    float* out = (float*)d_out;

    cudaFuncSetAttribute(scores_kernel,
                         cudaFuncAttributeMaxDynamicSharedMemorySize,
                         SCORES_SMEM_BYTES);

    init_kernel<<<(BN * HWN + 255) / 256, 256>>>();

    dim3 gq(HWN / 64, CN / 64, BN);
    qkv_kernel<<<gq, 256>>>(fuse, Wq, bq, Wk, bk, Wv, bv);

    qmask_kernel<<<(4 * HWN + 255) / 256, 256>>>();

    dim3 gs(HWN / 64, HWN / 64);
    scores_kernel<<<gs, 256, SCORES_SMEM_BYTES>>>();

    m2_kernel<<<1, 256>>>();

    out_kernel<<<(BN * CHWN / 4 + 255) / 256, 256>>>(out);
}